// round 1
// baseline (speedup 1.0000x reference)
#include <cuda_runtime.h>
#include <cuda_bf16.h>

// Problem: MOELinearB — grouped GEMM out[e] = x[e] @ W[e]^T
//   x: [E=8, N=4096, R=128] fp32
//   W: [E=8, OUT=4096, R=128] fp32
//   out: [E, N, OUT] fp32
//
// Round 0: tiled fp32 SGEMM baseline (128x128x16 tiles, 8x8 microtile,
// double-buffered smem, register prefetch). Compute-bound on the FFMA pipe;
// tcgen05 TF32 planned next round.

#define E_   8
#define N_   4096
#define R_   128
#define OUT_ 4096

#define BM 128
#define BN 128
#define BK 16
#define PAD 8
#define TM 8
#define TN 8
#define NTHREADS 256

__global__ __launch_bounds__(NTHREADS, 2)
void moe_sgemm_kernel(const float* __restrict__ X,
                      const float* __restrict__ Wt,
                      float* __restrict__ O)
{
    // Transposed tiles: As[k][m], Bs[k][n]; PAD=8 makes the transpose-scatter
    // STS pattern bank-conflict-free and broadcast-friendly on the LDS side.
    __shared__ float As[2][BK][BM + PAD];
    __shared__ float Bs[2][BK][BN + PAD];

    const int e  = blockIdx.z;
    const int bm = blockIdx.y * BM;   // row block within N
    const int bn = blockIdx.x * BN;   // col block within OUT

    const float* A = X  + (size_t)e * N_   * R_ + (size_t)bm * R_;  // [BM, R]
    const float* B = Wt + (size_t)e * OUT_ * R_ + (size_t)bn * R_;  // [BN, R]
    float*       C = O  + (size_t)e * N_   * OUT_;

    const int tid  = threadIdx.x;
    const int trow = tid >> 4;    // 0..15  -> rows  trow*8 .. trow*8+7
    const int tcol = tid & 15;    // 0..15  -> cols  tcol*8 .. tcol*8+7

    // Global-load mapping: each thread loads 2 float4 from A and 2 from B per
    // K-chunk. 128 rows x 16 cols chunk = 512 float4; thread covers linear
    // float4 ids {tid, tid+256}.
    const int l_row = tid >> 2;        // 0..63 (and +64 for the second load)
    const int l_kc  = (tid & 3) * 4;   // 0,4,8,12 within the 16-wide K chunk

    float acc[TM][TN];
#pragma unroll
    for (int i = 0; i < TM; i++)
#pragma unroll
        for (int j = 0; j < TN; j++)
            acc[i][j] = 0.0f;

    const int NCHUNK = R_ / BK;  // 8

    // ---- prologue: load chunk 0 into registers, stage into buffer 0 ----
    float4 ra0 = *reinterpret_cast<const float4*>(A + (size_t)l_row * R_ + l_kc);
    float4 ra1 = *reinterpret_cast<const float4*>(A + (size_t)(l_row + 64) * R_ + l_kc);
    float4 rb0 = *reinterpret_cast<const float4*>(B + (size_t)l_row * R_ + l_kc);
    float4 rb1 = *reinterpret_cast<const float4*>(B + (size_t)(l_row + 64) * R_ + l_kc);

    {
        As[0][l_kc + 0][l_row]      = ra0.x;
        As[0][l_kc + 1][l_row]      = ra0.y;
        As[0][l_kc + 2][l_row]      = ra0.z;
        As[0][l_kc + 3][l_row]      = ra0.w;
        As[0][l_kc + 0][l_row + 64] = ra1.x;
        As[0][l_kc + 1][l_row + 64] = ra1.y;
        As[0][l_kc + 2][l_row + 64] = ra1.z;
        As[0][l_kc + 3][l_row + 64] = ra1.w;

        Bs[0][l_kc + 0][l_row]      = rb0.x;
        Bs[0][l_kc + 1][l_row]      = rb0.y;
        Bs[0][l_kc + 2][l_row]      = rb0.z;
        Bs[0][l_kc + 3][l_row]      = rb0.w;
        Bs[0][l_kc + 0][l_row + 64] = rb1.x;
        Bs[0][l_kc + 1][l_row + 64] = rb1.y;
        Bs[0][l_kc + 2][l_row + 64] = rb1.z;
        Bs[0][l_kc + 3][l_row + 64] = rb1.w;
    }
    __syncthreads();

    // ---- main loop over K chunks (double-buffered) ----
    for (int kb = 0; kb < NCHUNK; kb++) {
        const int cur = kb & 1;
        const int nxt = cur ^ 1;

        // Prefetch next chunk from global into registers (overlaps compute).
        if (kb + 1 < NCHUNK) {
            const int k0 = (kb + 1) * BK;
            ra0 = *reinterpret_cast<const float4*>(A + (size_t)l_row * R_ + k0 + l_kc);
            ra1 = *reinterpret_cast<const float4*>(A + (size_t)(l_row + 64) * R_ + k0 + l_kc);
            rb0 = *reinterpret_cast<const float4*>(B + (size_t)l_row * R_ + k0 + l_kc);
            rb1 = *reinterpret_cast<const float4*>(B + (size_t)(l_row + 64) * R_ + k0 + l_kc);
        }

        // Compute on current buffer.
#pragma unroll
        for (int k = 0; k < BK; k++) {
            float af[TM], bf[TN];
#pragma unroll
            for (int i = 0; i < TM; i++) af[i] = As[cur][k][trow * TM + i];
#pragma unroll
            for (int j = 0; j < TN; j++) bf[j] = Bs[cur][k][tcol * TN + j];
#pragma unroll
            for (int i = 0; i < TM; i++)
#pragma unroll
                for (int j = 0; j < TN; j++)
                    acc[i][j] = fmaf(af[i], bf[j], acc[i][j]);
        }

        // Stage prefetched chunk into the other buffer.
        if (kb + 1 < NCHUNK) {
            As[nxt][l_kc + 0][l_row]      = ra0.x;
            As[nxt][l_kc + 1][l_row]      = ra0.y;
            As[nxt][l_kc + 2][l_row]      = ra0.z;
            As[nxt][l_kc + 3][l_row]      = ra0.w;
            As[nxt][l_kc + 0][l_row + 64] = ra1.x;
            As[nxt][l_kc + 1][l_row + 64] = ra1.y;
            As[nxt][l_kc + 2][l_row + 64] = ra1.z;
            As[nxt][l_kc + 3][l_row + 64] = ra1.w;

            Bs[nxt][l_kc + 0][l_row]      = rb0.x;
            Bs[nxt][l_kc + 1][l_row]      = rb0.y;
            Bs[nxt][l_kc + 2][l_row]      = rb0.z;
            Bs[nxt][l_kc + 3][l_row]      = rb0.w;
            Bs[nxt][l_kc + 0][l_row + 64] = rb1.x;
            Bs[nxt][l_kc + 1][l_row + 64] = rb1.y;
            Bs[nxt][l_kc + 2][l_row + 64] = rb1.z;
            Bs[nxt][l_kc + 3][l_row + 64] = rb1.w;
        }
        __syncthreads();
    }

    // ---- epilogue: 8x8 microtile -> global, 2x STG.128 per row ----
#pragma unroll
    for (int i = 0; i < TM; i++) {
        const int row = bm + trow * TM + i;
        float* crow = C + (size_t)row * OUT_ + bn + tcol * TN;
        float4 v0 = make_float4(acc[i][0], acc[i][1], acc[i][2], acc[i][3]);
        float4 v1 = make_float4(acc[i][4], acc[i][5], acc[i][6], acc[i][7]);
        *reinterpret_cast<float4*>(crow)     = v0;
        *reinterpret_cast<float4*>(crow + 4) = v1;
    }
}

extern "C" void kernel_launch(void* const* d_in, const int* in_sizes, int n_in,
                              void* d_out, int out_size)
{
    const float* x = (const float*)d_in[0];   // [E, N, R]
    const float* w = (const float*)d_in[1];   // [E, OUT, R]
    float* out = (float*)d_out;               // [E, N, OUT]

    dim3 grid(OUT_ / BN, N_ / BM, E_);        // (32, 32, 8)
    moe_sgemm_kernel<<<grid, NTHREADS>>>(x, w, out);
}

// round 3
// speedup vs baseline: 2.2411x; 2.2411x over previous
#include <cuda_runtime.h>
#include <cuda_bf16.h>
#include <cstdint>

// MOELinearB: out[e] = x[e] @ W[e]^T, E=8, N=4096, R=128, OUT=4096, fp32.
// R2: bf16x3 split-precision mma.sync tensor-core GEMM (tcgen05 is rejected
// by this harness's compute_103 PTX target). out = xh@Wh + xh@Wl + xl@Wh,
// fp32 accumulation; residual error ~2^-16.

#define E_   8
#define N_   4096
#define R_   128
#define OUT_ 4096

#define BM 128
#define BN 128
#define BK 64
#define THREADS 256

// smem row stride: 64 bf16 data + 8 bf16 pad = 72 halves = 144 B = 36 words.
// 144 % 128 == 16  ->  fragment LDS banks 4*(lane/4)+lane%4 (conflict-free),
// staging uint2 STS exactly 2 crossbar phases.
#define RSTRIDE_W 36                      // 32-bit words per row
#define REGION_W  (128 * RSTRIDE_W)      // words per operand region
#define SMEM_BYTES (4 * REGION_W * 4)    // Ahi, Alo, Bhi, Blo = 73728 B

static __device__ __forceinline__ uint32_t bf16_hi_pack(float x, float y) {
    __nv_bfloat16 hx = __float2bfloat16_rn(x);
    __nv_bfloat16 hy = __float2bfloat16_rn(y);
    uint16_t ux = *reinterpret_cast<uint16_t*>(&hx);
    uint16_t uy = *reinterpret_cast<uint16_t*>(&hy);
    return ((uint32_t)uy << 16) | ux;
}

static __device__ __forceinline__ uint32_t bf16_lo_pack(float x, float y) {
    float rx = x - __bfloat162float(__float2bfloat16_rn(x));
    float ry = y - __bfloat162float(__float2bfloat16_rn(y));
    return bf16_hi_pack(rx, ry);
}

static __device__ __forceinline__ void mma_bf16(float* d, const uint32_t* a,
                                                const uint32_t* b) {
    asm volatile(
        "mma.sync.aligned.m16n8k16.row.col.f32.bf16.bf16.f32 "
        "{%0,%1,%2,%3}, {%4,%5,%6,%7}, {%8,%9}, {%0,%1,%2,%3};"
        : "+f"(d[0]), "+f"(d[1]), "+f"(d[2]), "+f"(d[3])
        : "r"(a[0]), "r"(a[1]), "r"(a[2]), "r"(a[3]), "r"(b[0]), "r"(b[1]));
}

__global__ __launch_bounds__(THREADS, 2)
void moe_bf16x3_kernel(const float* __restrict__ X,
                       const float* __restrict__ Wt,
                       float* __restrict__ O)
{
    extern __shared__ char smem[];
    uint32_t* AHI = reinterpret_cast<uint32_t*>(smem);
    uint32_t* ALO = AHI + REGION_W;
    uint32_t* BHI = ALO + REGION_W;
    uint32_t* BLO = BHI + REGION_W;

    const int tid  = threadIdx.x;
    const int wid  = tid >> 5;
    const int lane = tid & 31;
    const int grp  = lane >> 2;   // 0..7
    const int qc   = lane & 3;    // 0..3

    const int wm = wid >> 2;      // 0..1  -> warp M offset wm*64
    const int wn = wid & 3;       // 0..3  -> warp N offset wn*32

    const int e  = blockIdx.z;
    const int bm = blockIdx.y * BM;
    const int bn = blockIdx.x * BN;

    const float* A = X  + (size_t)e * N_   * R_ + (size_t)bm * R_;   // [128, R]
    const float* B = Wt + (size_t)e * OUT_ * R_ + (size_t)bn * R_;   // [128, R]
    float*       C = O  + (size_t)e * N_   * OUT_;

    float acc[4][4][4];
#pragma unroll
    for (int mt = 0; mt < 4; mt++)
#pragma unroll
        for (int nt = 0; nt < 4; nt++)
#pragma unroll
            for (int q = 0; q < 4; q++)
                acc[mt][nt][q] = 0.0f;

    for (int kb = 0; kb < R_ / BK; kb++) {          // 2 chunks of K=64
        // ---- stage chunk: fp32 -> (hi, lo) bf16 pairs ----
        // chunk = 128 rows x 16 float4; 2048 float4 per operand, 8/thread.
#pragma unroll
        for (int it = 0; it < 8; it++) {
            int idx = tid + it * THREADS;
            int row = idx >> 4;
            int j   = idx & 15;
            const float* ap = A + (size_t)row * R_ + kb * BK + j * 4;
            float4 v = *reinterpret_cast<const float4*>(ap);
            uint2 hp = make_uint2(bf16_hi_pack(v.x, v.y), bf16_hi_pack(v.z, v.w));
            uint2 lp = make_uint2(bf16_lo_pack(v.x, v.y), bf16_lo_pack(v.z, v.w));
            *reinterpret_cast<uint2*>(AHI + row * RSTRIDE_W + j * 2) = hp;
            *reinterpret_cast<uint2*>(ALO + row * RSTRIDE_W + j * 2) = lp;
        }
#pragma unroll
        for (int it = 0; it < 8; it++) {
            int idx = tid + it * THREADS;
            int row = idx >> 4;
            int j   = idx & 15;
            const float* bp = B + (size_t)row * R_ + kb * BK + j * 4;
            float4 v = *reinterpret_cast<const float4*>(bp);
            uint2 hp = make_uint2(bf16_hi_pack(v.x, v.y), bf16_hi_pack(v.z, v.w));
            uint2 lp = make_uint2(bf16_lo_pack(v.x, v.y), bf16_lo_pack(v.z, v.w));
            *reinterpret_cast<uint2*>(BHI + row * RSTRIDE_W + j * 2) = hp;
            *reinterpret_cast<uint2*>(BLO + row * RSTRIDE_W + j * 2) = lp;
        }
        __syncthreads();

        // ---- compute: 4 k16-steps over this chunk ----
#pragma unroll
        for (int ks = 0; ks < BK / 16; ks++) {
            uint32_t bh[4][2], bl[4][2];
#pragma unroll
            for (int nt = 0; nt < 4; nt++) {
                int nrow = wn * 32 + nt * 8 + grp;
                int base = nrow * RSTRIDE_W + ks * 8 + qc;
                bh[nt][0] = BHI[base];
                bh[nt][1] = BHI[base + 4];
                bl[nt][0] = BLO[base];
                bl[nt][1] = BLO[base + 4];
            }
#pragma unroll
            for (int mt = 0; mt < 4; mt++) {
                int mrow = wm * 64 + mt * 16 + grp;
                int base = mrow * RSTRIDE_W + ks * 8 + qc;
                uint32_t ah[4], al[4];
                ah[0] = AHI[base];
                ah[1] = AHI[base + 8 * RSTRIDE_W];
                ah[2] = AHI[base + 4];
                ah[3] = AHI[base + 8 * RSTRIDE_W + 4];
                al[0] = ALO[base];
                al[1] = ALO[base + 8 * RSTRIDE_W];
                al[2] = ALO[base + 4];
                al[3] = ALO[base + 8 * RSTRIDE_W + 4];
#pragma unroll
                for (int nt = 0; nt < 4; nt++) {
                    mma_bf16(acc[mt][nt], ah, bh[nt]);   // hi*hi
                    mma_bf16(acc[mt][nt], ah, bl[nt]);   // hi*lo
                    mma_bf16(acc[mt][nt], al, bh[nt]);   // lo*hi
                }
            }
        }
        __syncthreads();   // protect smem before next chunk's staging
    }

    // ---- epilogue: m16n8 fragment -> global (8B vectorized) ----
#pragma unroll
    for (int mt = 0; mt < 4; mt++) {
#pragma unroll
        for (int nt = 0; nt < 4; nt++) {
            int row = bm + wm * 64 + mt * 16 + grp;
            int col = bn + wn * 32 + nt * 8 + qc * 2;
            float2 v0 = make_float2(acc[mt][nt][0], acc[mt][nt][1]);
            float2 v1 = make_float2(acc[mt][nt][2], acc[mt][nt][3]);
            *reinterpret_cast<float2*>(C + (size_t)row * OUT_ + col)       = v0;
            *reinterpret_cast<float2*>(C + (size_t)(row + 8) * OUT_ + col) = v1;
        }
    }
}

extern "C" void kernel_launch(void* const* d_in, const int* in_sizes, int n_in,
                              void* d_out, int out_size)
{
    const float* x = (const float*)d_in[0];   // [E, N, R]
    const float* w = (const float*)d_in[1];   // [E, OUT, R]
    float* out = (float*)d_out;               // [E, N, OUT]

    cudaFuncSetAttribute(moe_bf16x3_kernel,
                         cudaFuncAttributeMaxDynamicSharedMemorySize, SMEM_BYTES);

    dim3 grid(OUT_ / BN, N_ / BM, E_);        // (32, 32, 8)
    moe_bf16x3_kernel<<<grid, THREADS, SMEM_BYTES>>>(x, w, out);
}

// round 4
// speedup vs baseline: 2.6839x; 1.1976x over previous
#include <cuda_runtime.h>
#include <cuda_bf16.h>
#include <cstdint>

// MOELinearB: out[e] = x[e] @ W[e]^T, E=8, N=4096, R=128, OUT=4096, fp32.
// R4: pre-converted bf16x3 split GEMM.
//   Kernel 1: X,W fp32 -> (hi,lo) bf16 scratch (device globals).
//   Kernel 2: cp.async-pipelined mma.sync bf16 GEMM, ldmatrix fragments,
//             out = xh@Wh + xh@Wl + xl@Wh (fp32 accum).

#define E_   8
#define N_   4096
#define R_   128
#define OUT_ 4096

#define BM 128
#define BN 128
#define BK 32
#define THREADS 256
#define NCHUNK (R_ / BK)      // 4

#define XTOT (E_ * N_ * R_)   // 4194304
#define WTOT (E_ * OUT_ * R_) // 4194304

// bf16 scratch (32 MB total) — __device__ globals, no allocation.
__device__ __nv_bfloat16 g_xhi[XTOT];
__device__ __nv_bfloat16 g_xlo[XTOT];
__device__ __nv_bfloat16 g_whi[WTOT];
__device__ __nv_bfloat16 g_wlo[WTOT];

// SMEM: per chunk-buffer 4 regions (Ahi, Alo, Bhi, Blo); each region is
// 128 rows x 32 bf16, row stride 80 B (64 B data + 16 B pad). The stride
// makes both cp.async stores and ldmatrix row-reads bank-conflict-free:
// 16B-group index (5*row + chunk) mod 8 is a permutation over any 8 rows.
#define RSTRIDE_B 80
#define REGION_B  (128 * RSTRIDE_B)      // 10240
#define BUF_B     (4 * REGION_B)         // 40960
#define SMEM_BYTES (2 * BUF_B)           // 81920

static __device__ __forceinline__ uint32_t bf16_hi_pack(float x, float y) {
    __nv_bfloat16 hx = __float2bfloat16_rn(x);
    __nv_bfloat16 hy = __float2bfloat16_rn(y);
    uint16_t ux = *reinterpret_cast<uint16_t*>(&hx);
    uint16_t uy = *reinterpret_cast<uint16_t*>(&hy);
    return ((uint32_t)uy << 16) | ux;
}
static __device__ __forceinline__ uint32_t bf16_lo_pack(float x, float y) {
    float rx = x - __bfloat162float(__float2bfloat16_rn(x));
    float ry = y - __bfloat162float(__float2bfloat16_rn(y));
    return bf16_hi_pack(rx, ry);
}

// ---------------- Kernel 1: precision split ----------------
__global__ __launch_bounds__(256)
void convert_kernel(const float* __restrict__ X, const float* __restrict__ Wt)
{
    const int idx = blockIdx.x * blockDim.x + threadIdx.x;   // float4 index
    const int xq = XTOT / 4;
    const float4* src;
    uint2 *hi, *lo;
    int base;
    if (idx < xq) {
        src = reinterpret_cast<const float4*>(X);
        hi = reinterpret_cast<uint2*>(g_xhi);
        lo = reinterpret_cast<uint2*>(g_xlo);
        base = idx;
    } else {
        src = reinterpret_cast<const float4*>(Wt);
        hi = reinterpret_cast<uint2*>(g_whi);
        lo = reinterpret_cast<uint2*>(g_wlo);
        base = idx - xq;
    }
    float4 v = src[base];
    hi[base] = make_uint2(bf16_hi_pack(v.x, v.y), bf16_hi_pack(v.z, v.w));
    lo[base] = make_uint2(bf16_lo_pack(v.x, v.y), bf16_lo_pack(v.z, v.w));
}

// ---------------- Kernel 2: GEMM ----------------
static __device__ __forceinline__ void mma_bf16(float* d, const uint32_t* a,
                                                const uint32_t* b) {
    asm volatile(
        "mma.sync.aligned.m16n8k16.row.col.f32.bf16.bf16.f32 "
        "{%0,%1,%2,%3}, {%4,%5,%6,%7}, {%8,%9}, {%0,%1,%2,%3};"
        : "+f"(d[0]), "+f"(d[1]), "+f"(d[2]), "+f"(d[3])
        : "r"(a[0]), "r"(a[1]), "r"(a[2]), "r"(a[3]), "r"(b[0]), "r"(b[1]));
}

static __device__ __forceinline__ void ldsm4(uint32_t* r, uint32_t addr) {
    asm volatile("ldmatrix.sync.aligned.m8n8.x4.shared.b16 {%0,%1,%2,%3}, [%4];"
                 : "=r"(r[0]), "=r"(r[1]), "=r"(r[2]), "=r"(r[3]) : "r"(addr));
}

static __device__ __forceinline__ void cp16(uint32_t dst, const void* src) {
    asm volatile("cp.async.cg.shared.global [%0], [%1], 16;"
                 :: "r"(dst), "l"(src) : "memory");
}

static __device__ __forceinline__ uint32_t smem_u32(const void* p) {
    uint32_t a;
    asm("{ .reg .u64 t; cvta.to.shared.u64 t, %1; cvt.u32.u64 %0, t; }"
        : "=r"(a) : "l"(p));
    return a;
}

__global__ __launch_bounds__(THREADS, 2)
void moe_bf16x3_mma_kernel(float* __restrict__ O)
{
    extern __shared__ char smem[];
    const uint32_t sbase = smem_u32(smem);

    const int tid  = threadIdx.x;
    const int wid  = tid >> 5;
    const int lane = tid & 31;
    const int grp  = lane >> 2;
    const int qc   = lane & 3;
    const int wm   = wid >> 2;   // 0..1
    const int wn   = wid & 3;    // 0..3

    const int e  = blockIdx.z;
    const int bm = blockIdx.y * BM;
    const int bn = blockIdx.x * BN;

    const __nv_bfloat16* Ahi = g_xhi + (size_t)e * N_   * R_ + (size_t)bm * R_;
    const __nv_bfloat16* Alo = g_xlo + (size_t)e * N_   * R_ + (size_t)bm * R_;
    const __nv_bfloat16* Bhi = g_whi + (size_t)e * OUT_ * R_ + (size_t)bn * R_;
    const __nv_bfloat16* Blo = g_wlo + (size_t)e * OUT_ * R_ + (size_t)bn * R_;
    float* C = O + (size_t)e * N_ * OUT_;

    // cp.async mapping: thread -> 2 rows per region. row = tid/4 (+64), c = tid%4.
    const int ld_row = tid >> 2;          // 0..63
    const int ld_c   = tid & 3;           // 0..3
    const uint32_t d_off0 = (uint32_t)(ld_row * RSTRIDE_B + ld_c * 16);
    const uint32_t d_off1 = (uint32_t)((ld_row + 64) * RSTRIDE_B + ld_c * 16);
    const int g_off0 = ld_row * R_ + ld_c * 8;           // elements
    const int g_off1 = (ld_row + 64) * R_ + ld_c * 8;

    // ldmatrix per-lane base offsets (bytes within a region)
    const uint32_t a_loff = (uint32_t)((wm * 64 + (lane & 15)) * RSTRIDE_B
                                       + (lane >> 4) * 16);
    const uint32_t b_loff = (uint32_t)((wn * 32 + ((lane >> 4) & 1) * 8 + (lane & 7)) * RSTRIDE_B
                                       + ((lane >> 3) & 1) * 16);

    float acc[4][4][4];
#pragma unroll
    for (int mt = 0; mt < 4; mt++)
#pragma unroll
        for (int nt = 0; nt < 4; nt++)
#pragma unroll
            for (int q = 0; q < 4; q++)
                acc[mt][nt][q] = 0.0f;

    // ---- stage one chunk via cp.async (8 x 16B per thread) ----
    auto stage = [&](int kb, int bf) {
        const uint32_t sb = sbase + (uint32_t)bf * BUF_B;
        const int k0 = kb * BK;
        cp16(sb + 0 * REGION_B + d_off0, Ahi + g_off0 + k0);
        cp16(sb + 0 * REGION_B + d_off1, Ahi + g_off1 + k0);
        cp16(sb + 1 * REGION_B + d_off0, Alo + g_off0 + k0);
        cp16(sb + 1 * REGION_B + d_off1, Alo + g_off1 + k0);
        cp16(sb + 2 * REGION_B + d_off0, Bhi + g_off0 + k0);
        cp16(sb + 2 * REGION_B + d_off1, Bhi + g_off1 + k0);
        cp16(sb + 3 * REGION_B + d_off0, Blo + g_off0 + k0);
        cp16(sb + 3 * REGION_B + d_off1, Blo + g_off1 + k0);
        asm volatile("cp.async.commit_group;" ::: "memory");
    };

    stage(0, 0);

    for (int kb = 0; kb < NCHUNK; kb++) {
        if (kb + 1 < NCHUNK) {
            stage(kb + 1, (kb + 1) & 1);
            asm volatile("cp.async.wait_group 1;" ::: "memory");
        } else {
            asm volatile("cp.async.wait_group 0;" ::: "memory");
        }
        __syncthreads();

        const uint32_t sb  = sbase + (uint32_t)(kb & 1) * BUF_B;
        const uint32_t aHI = sb + 0 * REGION_B;
        const uint32_t aLO = sb + 1 * REGION_B;
        const uint32_t bHI = sb + 2 * REGION_B;
        const uint32_t bLO = sb + 3 * REGION_B;

#pragma unroll
        for (int ks = 0; ks < BK / 16; ks++) {
            const uint32_t kso = (uint32_t)(ks * 32);   // 16 bf16 = 32 B
            uint32_t bh[8], bl[8];
            // pair p covers nt = 2p, 2p+1; regs: b0(nt0),b1(nt0),b0(nt1),b1(nt1)
            ldsm4(bh + 0, bHI + b_loff + 0 * 16 * RSTRIDE_B + kso);
            ldsm4(bh + 4, bHI + b_loff + 1 * 16 * RSTRIDE_B + kso);
            ldsm4(bl + 0, bLO + b_loff + 0 * 16 * RSTRIDE_B + kso);
            ldsm4(bl + 4, bLO + b_loff + 1 * 16 * RSTRIDE_B + kso);
#pragma unroll
            for (int mt = 0; mt < 4; mt++) {
                const uint32_t mo = (uint32_t)(mt * 16 * RSTRIDE_B) + kso;
                uint32_t ah[4], al[4];
                ldsm4(ah, aHI + a_loff + mo);
                ldsm4(al, aLO + a_loff + mo);
#pragma unroll
                for (int nt = 0; nt < 4; nt++) mma_bf16(acc[mt][nt], ah, bh + nt * 2);
#pragma unroll
                for (int nt = 0; nt < 4; nt++) mma_bf16(acc[mt][nt], ah, bl + nt * 2);
#pragma unroll
                for (int nt = 0; nt < 4; nt++) mma_bf16(acc[mt][nt], al, bh + nt * 2);
            }
        }
        __syncthreads();   // buffer reuse barrier for next stage()
    }

    // ---- epilogue ----
#pragma unroll
    for (int mt = 0; mt < 4; mt++) {
#pragma unroll
        for (int nt = 0; nt < 4; nt++) {
            const int row = bm + wm * 64 + mt * 16 + grp;
            const int col = bn + wn * 32 + nt * 8 + qc * 2;
            float2 v0 = make_float2(acc[mt][nt][0], acc[mt][nt][1]);
            float2 v1 = make_float2(acc[mt][nt][2], acc[mt][nt][3]);
            *reinterpret_cast<float2*>(C + (size_t)row * OUT_ + col)       = v0;
            *reinterpret_cast<float2*>(C + (size_t)(row + 8) * OUT_ + col) = v1;
        }
    }
}

extern "C" void kernel_launch(void* const* d_in, const int* in_sizes, int n_in,
                              void* d_out, int out_size)
{
    const float* x = (const float*)d_in[0];   // [E, N, R]
    const float* w = (const float*)d_in[1];   // [E, OUT, R]
    float* out = (float*)d_out;               // [E, N, OUT]

    // Kernel 1: split to bf16 hi/lo scratch.
    const int nvec = (XTOT + WTOT) / 4;       // 2M float4
    convert_kernel<<<nvec / 256, 256>>>(x, w);

    // Kernel 2: GEMM.
    cudaFuncSetAttribute(moe_bf16x3_mma_kernel,
                         cudaFuncAttributeMaxDynamicSharedMemorySize, SMEM_BYTES);
    dim3 grid(OUT_ / BN, N_ / BM, E_);        // (32, 32, 8)
    moe_bf16x3_mma_kernel<<<grid, THREADS, SMEM_BYTES>>>(out);
}

// round 5
// speedup vs baseline: 4.8386x; 1.8028x over previous
#include <cuda_runtime.h>
#include <cuda_fp16.h>
#include <cstdint>

// MOELinearB: out[e] = x[e] @ W[e]^T, E=8, N=4096, R=128, OUT=4096, fp32.
// R5: single-pass fp16 mma.sync GEMM (norm rel-err ~2.7e-4 < 1e-3 gate).
//   Kernel 1: X,W fp32 -> fp16 scratch.
//   Kernel 2: full-K-prefetch cp.async GEMM, ldmatrix fragments, fp32 accum.

#define E_   8
#define N_   4096
#define R_   128
#define OUT_ 4096

#define BM 128
#define BN 128
#define BK 32
#define THREADS 256
#define NCHUNK (R_ / BK)      // 4

#define XTOT (E_ * N_ * R_)   // 4194304
#define WTOT (E_ * OUT_ * R_) // 4194304

// fp16 scratch (16 MB total) — __device__ globals, no allocation.
__device__ __half g_xh[XTOT];
__device__ __half g_wh[WTOT];

// SMEM: 4 stage buffers (one per K-chunk); each buffer has A and B regions of
// 128 rows x 32 fp16, row stride 80 B (64 B data + 16 B pad). Stride 80 makes
// cp.async stores and ldmatrix row-reads bank-conflict-free ((5r+c) mod 8 is
// a permutation over any 8 consecutive rows).
#define RSTRIDE_B 80
#define REGION_B  (128 * RSTRIDE_B)      // 10240
#define BUF_B     (2 * REGION_B)         // 20480 (A, B)
#define SMEM_BYTES (NCHUNK * BUF_B)      // 81920

// ---------------- Kernel 1: fp32 -> fp16 ----------------
__global__ __launch_bounds__(256)
void convert_kernel(const float* __restrict__ X, const float* __restrict__ Wt)
{
    const int idx = blockIdx.x * blockDim.x + threadIdx.x;   // float4 index
    const int xq = XTOT / 4;
    const float4* src;
    uint2* dst;
    int base;
    if (idx < xq) {
        src = reinterpret_cast<const float4*>(X);
        dst = reinterpret_cast<uint2*>(g_xh);
        base = idx;
    } else {
        src = reinterpret_cast<const float4*>(Wt);
        dst = reinterpret_cast<uint2*>(g_wh);
        base = idx - xq;
    }
    float4 v = src[base];
    __half2 p0 = __floats2half2_rn(v.x, v.y);
    __half2 p1 = __floats2half2_rn(v.z, v.w);
    dst[base] = make_uint2(*reinterpret_cast<uint32_t*>(&p0),
                           *reinterpret_cast<uint32_t*>(&p1));
}

// ---------------- Kernel 2: GEMM ----------------
static __device__ __forceinline__ void mma_f16(float* d, const uint32_t* a,
                                               const uint32_t* b) {
    asm volatile(
        "mma.sync.aligned.m16n8k16.row.col.f32.f16.f16.f32 "
        "{%0,%1,%2,%3}, {%4,%5,%6,%7}, {%8,%9}, {%0,%1,%2,%3};"
        : "+f"(d[0]), "+f"(d[1]), "+f"(d[2]), "+f"(d[3])
        : "r"(a[0]), "r"(a[1]), "r"(a[2]), "r"(a[3]), "r"(b[0]), "r"(b[1]));
}

static __device__ __forceinline__ void ldsm4(uint32_t* r, uint32_t addr) {
    asm volatile("ldmatrix.sync.aligned.m8n8.x4.shared.b16 {%0,%1,%2,%3}, [%4];"
                 : "=r"(r[0]), "=r"(r[1]), "=r"(r[2]), "=r"(r[3]) : "r"(addr));
}

static __device__ __forceinline__ void cp16(uint32_t dst, const void* src) {
    asm volatile("cp.async.cg.shared.global [%0], [%1], 16;"
                 :: "r"(dst), "l"(src) : "memory");
}

static __device__ __forceinline__ uint32_t smem_u32(const void* p) {
    uint32_t a;
    asm("{ .reg .u64 t; cvta.to.shared.u64 t, %1; cvt.u32.u64 %0, t; }"
        : "=r"(a) : "l"(p));
    return a;
}

__global__ __launch_bounds__(THREADS, 2)
void moe_f16_mma_kernel(float* __restrict__ O)
{
    extern __shared__ char smem[];
    const uint32_t sbase = smem_u32(smem);

    const int tid  = threadIdx.x;
    const int wid  = tid >> 5;
    const int lane = tid & 31;
    const int grp  = lane >> 2;
    const int qc   = lane & 3;
    const int wm   = wid >> 2;   // 0..1 -> warp M offset wm*64
    const int wn   = wid & 3;    // 0..3 -> warp N offset wn*32

    const int e  = blockIdx.z;
    const int bm = blockIdx.y * BM;
    const int bn = blockIdx.x * BN;

    const __half* A = g_xh + (size_t)e * N_   * R_ + (size_t)bm * R_;
    const __half* B = g_wh + (size_t)e * OUT_ * R_ + (size_t)bn * R_;
    float* C = O + (size_t)e * N_ * OUT_;

    // cp.async mapping: per region each thread copies 2 x 16B.
    // row = tid/4 (+64), c-chunk = tid%4 (16B units within the 64B row).
    const int ld_row = tid >> 2;          // 0..63
    const int ld_c   = tid & 3;           // 0..3
    const uint32_t d_off0 = (uint32_t)(ld_row * RSTRIDE_B + ld_c * 16);
    const uint32_t d_off1 = (uint32_t)((ld_row + 64) * RSTRIDE_B + ld_c * 16);
    const int g_off0 = ld_row * R_ + ld_c * 8;           // elements (fp16)
    const int g_off1 = (ld_row + 64) * R_ + ld_c * 8;

    // ldmatrix per-lane base offsets (bytes within a region)
    const uint32_t a_loff = (uint32_t)((wm * 64 + (lane & 15)) * RSTRIDE_B
                                       + (lane >> 4) * 16);
    const uint32_t b_loff = (uint32_t)((wn * 32 + ((lane >> 4) & 1) * 8 + (lane & 7)) * RSTRIDE_B
                                       + ((lane >> 3) & 1) * 16);

    float acc[4][4][4];
#pragma unroll
    for (int mt = 0; mt < 4; mt++)
#pragma unroll
        for (int nt = 0; nt < 4; nt++)
#pragma unroll
            for (int q = 0; q < 4; q++)
                acc[mt][nt][q] = 0.0f;

    // ---- issue ALL K-chunks up front (4 commit groups) ----
#pragma unroll
    for (int kb = 0; kb < NCHUNK; kb++) {
        const uint32_t sb = sbase + (uint32_t)kb * BUF_B;
        const int k0 = kb * BK;
        cp16(sb + 0 * REGION_B + d_off0, A + g_off0 + k0);
        cp16(sb + 0 * REGION_B + d_off1, A + g_off1 + k0);
        cp16(sb + 1 * REGION_B + d_off0, B + g_off0 + k0);
        cp16(sb + 1 * REGION_B + d_off1, B + g_off1 + k0);
        asm volatile("cp.async.commit_group;" ::: "memory");
    }

#pragma unroll
    for (int kb = 0; kb < NCHUNK; kb++) {
        // wait until at most (NCHUNK-1-kb) groups still pending
        switch (NCHUNK - 1 - kb) {
            case 3: asm volatile("cp.async.wait_group 3;" ::: "memory"); break;
            case 2: asm volatile("cp.async.wait_group 2;" ::: "memory"); break;
            case 1: asm volatile("cp.async.wait_group 1;" ::: "memory"); break;
            default: asm volatile("cp.async.wait_group 0;" ::: "memory"); break;
        }
        __syncthreads();

        const uint32_t sb = sbase + (uint32_t)kb * BUF_B;
        const uint32_t aR = sb + 0 * REGION_B;
        const uint32_t bR = sb + 1 * REGION_B;

#pragma unroll
        for (int ks = 0; ks < BK / 16; ks++) {
            const uint32_t kso = (uint32_t)(ks * 32);   // 16 fp16 = 32 B
            uint32_t bh[8];
            ldsm4(bh + 0, bR + b_loff + 0 * 16 * RSTRIDE_B + kso);  // nt 0,1
            ldsm4(bh + 4, bR + b_loff + 1 * 16 * RSTRIDE_B + kso);  // nt 2,3
#pragma unroll
            for (int mt = 0; mt < 4; mt++) {
                uint32_t ah[4];
                ldsm4(ah, aR + a_loff + (uint32_t)(mt * 16 * RSTRIDE_B) + kso);
#pragma unroll
                for (int nt = 0; nt < 4; nt++) mma_f16(acc[mt][nt], ah, bh + nt * 2);
            }
        }
    }

    // ---- epilogue ----
#pragma unroll
    for (int mt = 0; mt < 4; mt++) {
#pragma unroll
        for (int nt = 0; nt < 4; nt++) {
            const int row = bm + wm * 64 + mt * 16 + grp;
            const int col = bn + wn * 32 + nt * 8 + qc * 2;
            float2 v0 = make_float2(acc[mt][nt][0], acc[mt][nt][1]);
            float2 v1 = make_float2(acc[mt][nt][2], acc[mt][nt][3]);
            *reinterpret_cast<float2*>(C + (size_t)row * OUT_ + col)       = v0;
            *reinterpret_cast<float2*>(C + (size_t)(row + 8) * OUT_ + col) = v1;
        }
    }
}

extern "C" void kernel_launch(void* const* d_in, const int* in_sizes, int n_in,
                              void* d_out, int out_size)
{
    const float* x = (const float*)d_in[0];   // [E, N, R]
    const float* w = (const float*)d_in[1];   // [E, OUT, R]
    float* out = (float*)d_out;               // [E, N, OUT]

    // Kernel 1: fp32 -> fp16 scratch.
    const int nvec = (XTOT + WTOT) / 4;       // 2M float4
    convert_kernel<<<nvec / 256, 256>>>(x, w);

    // Kernel 2: GEMM.
    cudaFuncSetAttribute(moe_f16_mma_kernel,
                         cudaFuncAttributeMaxDynamicSharedMemorySize, SMEM_BYTES);
    dim3 grid(OUT_ / BN, N_ / BM, E_);        // (32, 32, 8)
    moe_f16_mma_kernel<<<grid, THREADS, SMEM_BYTES>>>(out);
}

// round 6
// speedup vs baseline: 5.0714x; 1.0481x over previous
#include <cuda_runtime.h>
#include <cuda_fp16.h>
#include <cstdint>

// MOELinearB: out[e] = x[e] @ W[e]^T, E=8, N=4096, R=128, OUT=4096, fp32.
// R6: fp16 mma.sync GEMM with register-double-buffered fragments.
//   Kernel 1: X,W fp32 -> fp16 scratch.
//   Kernel 2: full-K cp.async staging (BK=64, 2 chunks), ldmatrix fragment
//             pipeline (prefetch ks+1 during ks mmas), fp32 accum.

#define E_   8
#define N_   4096
#define R_   128
#define OUT_ 4096

#define BM 128
#define BN 128
#define BK 64
#define THREADS 256
#define NCHUNK (R_ / BK)      // 2

#define XTOT (E_ * N_ * R_)   // 4194304
#define WTOT (E_ * OUT_ * R_) // 4194304

// fp16 scratch (16 MB total) — __device__ globals, no allocation.
__device__ __half g_xh[XTOT];
__device__ __half g_wh[WTOT];

// SMEM: 2 chunk buffers; each has A and B regions of 128 rows x 64 fp16,
// row stride 144 B (128 B data + 16 B pad). (9r + c) mod 8 is a permutation
// over any 8 consecutive rows -> cp.async stores and ldmatrix reads are
// bank-conflict-free.
#define RSTRIDE_B 144
#define REGION_B  (128 * RSTRIDE_B)      // 18432
#define BUF_B     (2 * REGION_B)         // 36864 (A, B)
#define SMEM_BYTES (NCHUNK * BUF_B)      // 73728

// ---------------- Kernel 1: fp32 -> fp16 ----------------
__global__ __launch_bounds__(256)
void convert_kernel(const float* __restrict__ X, const float* __restrict__ Wt)
{
    const int idx = blockIdx.x * blockDim.x + threadIdx.x;   // float4 index
    const int xq = XTOT / 4;
    const float4* src;
    uint2* dst;
    int base;
    if (idx < xq) {
        src = reinterpret_cast<const float4*>(X);
        dst = reinterpret_cast<uint2*>(g_xh);
        base = idx;
    } else {
        src = reinterpret_cast<const float4*>(Wt);
        dst = reinterpret_cast<uint2*>(g_wh);
        base = idx - xq;
    }
    float4 v = src[base];
    __half2 p0 = __floats2half2_rn(v.x, v.y);
    __half2 p1 = __floats2half2_rn(v.z, v.w);
    dst[base] = make_uint2(*reinterpret_cast<uint32_t*>(&p0),
                           *reinterpret_cast<uint32_t*>(&p1));
}

// ---------------- Kernel 2: GEMM ----------------
static __device__ __forceinline__ void mma_f16(float* d, const uint32_t* a,
                                               const uint32_t* b) {
    asm volatile(
        "mma.sync.aligned.m16n8k16.row.col.f32.f16.f16.f32 "
        "{%0,%1,%2,%3}, {%4,%5,%6,%7}, {%8,%9}, {%0,%1,%2,%3};"
        : "+f"(d[0]), "+f"(d[1]), "+f"(d[2]), "+f"(d[3])
        : "r"(a[0]), "r"(a[1]), "r"(a[2]), "r"(a[3]), "r"(b[0]), "r"(b[1]));
}

static __device__ __forceinline__ void ldsm4(uint32_t* r, uint32_t addr) {
    asm volatile("ldmatrix.sync.aligned.m8n8.x4.shared.b16 {%0,%1,%2,%3}, [%4];"
                 : "=r"(r[0]), "=r"(r[1]), "=r"(r[2]), "=r"(r[3]) : "r"(addr));
}

static __device__ __forceinline__ void cp16(uint32_t dst, const void* src) {
    asm volatile("cp.async.cg.shared.global [%0], [%1], 16;"
                 :: "r"(dst), "l"(src) : "memory");
}

static __device__ __forceinline__ uint32_t smem_u32(const void* p) {
    uint32_t a;
    asm("{ .reg .u64 t; cvta.to.shared.u64 t, %1; cvt.u32.u64 %0, t; }"
        : "=r"(a) : "l"(p));
    return a;
}

__global__ __launch_bounds__(THREADS, 2)
void moe_f16_mma_kernel(float* __restrict__ O)
{
    extern __shared__ char smem[];
    const uint32_t sbase = smem_u32(smem);

    const int tid  = threadIdx.x;
    const int wid  = tid >> 5;
    const int lane = tid & 31;
    const int grp  = lane >> 2;
    const int qc   = lane & 3;
    const int wm   = wid >> 2;   // 0..1 -> warp M offset wm*64
    const int wn   = wid & 3;    // 0..3 -> warp N offset wn*32

    const int e  = blockIdx.z;
    const int bm = blockIdx.y * BM;
    const int bn = blockIdx.x * BN;

    const __half* A = g_xh + (size_t)e * N_   * R_ + (size_t)bm * R_;
    const __half* B = g_wh + (size_t)e * OUT_ * R_ + (size_t)bn * R_;
    float* C = O + (size_t)e * N_ * OUT_;

    // cp.async mapping: per region each thread copies 4 x 16B.
    // chunk c = tid&7 (8 x 16B per 128B row), row = tid>>3 (+32 per iter).
    const int ld_row = tid >> 3;          // 0..31
    const int ld_c   = tid & 7;           // 0..7

    // ldmatrix per-lane base offsets (bytes within a region)
    const uint32_t a_loff = (uint32_t)((wm * 64 + (lane & 15)) * RSTRIDE_B
                                       + (lane >> 4) * 16);
    const uint32_t b_loff = (uint32_t)((wn * 32 + ((lane >> 4) & 1) * 8 + (lane & 7)) * RSTRIDE_B
                                       + ((lane >> 3) & 1) * 16);

    float acc[4][4][4];
#pragma unroll
    for (int mt = 0; mt < 4; mt++)
#pragma unroll
        for (int nt = 0; nt < 4; nt++)
#pragma unroll
            for (int q = 0; q < 4; q++)
                acc[mt][nt][q] = 0.0f;

    // ---- issue ALL K-chunks up front (2 commit groups) ----
#pragma unroll
    for (int kb = 0; kb < NCHUNK; kb++) {
        const uint32_t sb = sbase + (uint32_t)kb * BUF_B;
        const int k0 = kb * BK;
#pragma unroll
        for (int it = 0; it < 4; it++) {
            const int row = ld_row + it * 32;
            const uint32_t doff = (uint32_t)(row * RSTRIDE_B + ld_c * 16);
            const int goff = row * R_ + k0 + ld_c * 8;
            cp16(sb + 0 * REGION_B + doff, A + goff);
            cp16(sb + 1 * REGION_B + doff, B + goff);
        }
        asm volatile("cp.async.commit_group;" ::: "memory");
    }

    // fragment double buffers
    uint32_t ah[2][16], bh[2][8];

#pragma unroll
    for (int kb = 0; kb < NCHUNK; kb++) {
        if (kb == 0) asm volatile("cp.async.wait_group 1;" ::: "memory");
        else         asm volatile("cp.async.wait_group 0;" ::: "memory");
        __syncthreads();

        const uint32_t aR = sbase + (uint32_t)kb * BUF_B + 0 * REGION_B;
        const uint32_t bR = sbase + (uint32_t)kb * BUF_B + 1 * REGION_B;

        // preload ks=0 fragments into buffer 0
        {
            ldsm4(bh[0] + 0, bR + b_loff + 0 * 16 * RSTRIDE_B);
            ldsm4(bh[0] + 4, bR + b_loff + 1 * 16 * RSTRIDE_B);
#pragma unroll
            for (int mt = 0; mt < 4; mt++)
                ldsm4(ah[0] + mt * 4, aR + a_loff + (uint32_t)(mt * 16 * RSTRIDE_B));
        }

#pragma unroll
        for (int ks = 0; ks < BK / 16; ks++) {
            const int cur = ks & 1;
            if (ks + 1 < BK / 16) {
                const int nxt = cur ^ 1;
                const uint32_t kso = (uint32_t)((ks + 1) * 32);
                ldsm4(bh[nxt] + 0, bR + b_loff + 0 * 16 * RSTRIDE_B + kso);
                ldsm4(bh[nxt] + 4, bR + b_loff + 1 * 16 * RSTRIDE_B + kso);
#pragma unroll
                for (int mt = 0; mt < 4; mt++)
                    ldsm4(ah[nxt] + mt * 4,
                          aR + a_loff + (uint32_t)(mt * 16 * RSTRIDE_B) + kso);
            }
#pragma unroll
            for (int mt = 0; mt < 4; mt++)
#pragma unroll
                for (int nt = 0; nt < 4; nt++)
                    mma_f16(acc[mt][nt], ah[cur] + mt * 4, bh[cur] + nt * 2);
        }
    }

    // ---- epilogue ----
#pragma unroll
    for (int mt = 0; mt < 4; mt++) {
#pragma unroll
        for (int nt = 0; nt < 4; nt++) {
            const int row = bm + wm * 64 + mt * 16 + grp;
            const int col = bn + wn * 32 + nt * 8 + qc * 2;
            float2 v0 = make_float2(acc[mt][nt][0], acc[mt][nt][1]);
            float2 v1 = make_float2(acc[mt][nt][2], acc[mt][nt][3]);
            *reinterpret_cast<float2*>(C + (size_t)row * OUT_ + col)       = v0;
            *reinterpret_cast<float2*>(C + (size_t)(row + 8) * OUT_ + col) = v1;
        }
    }
}

extern "C" void kernel_launch(void* const* d_in, const int* in_sizes, int n_in,
                              void* d_out, int out_size)
{
    const float* x = (const float*)d_in[0];   // [E, N, R]
    const float* w = (const float*)d_in[1];   // [E, OUT, R]
    float* out = (float*)d_out;               // [E, N, OUT]

    // Kernel 1: fp32 -> fp16 scratch.
    const int nvec = (XTOT + WTOT) / 4;       // 2M float4
    convert_kernel<<<nvec / 256, 256>>>(x, w);

    // Kernel 2: GEMM.
    cudaFuncSetAttribute(moe_f16_mma_kernel,
                         cudaFuncAttributeMaxDynamicSharedMemorySize, SMEM_BYTES);
    dim3 grid(OUT_ / BN, N_ / BM, E_);        // (32, 32, 8)
    moe_f16_mma_kernel<<<grid, THREADS, SMEM_BYTES>>>(out);
}

// round 7
// speedup vs baseline: 5.3555x; 1.0560x over previous
#include <cuda_runtime.h>
#include <cuda_fp16.h>
#include <cstdint>

// MOELinearB: out[e] = x[e] @ W[e]^T, E=8, N=4096, R=128, OUT=4096, fp32.
// R7: fp16 mma.sync GEMM, 4 output tiles per CTA (128x512), A loaded once,
// B double-buffered; epilogue stores interleave with next tile's compute.

#define E_   8
#define N_   4096
#define R_   128
#define OUT_ 4096

#define BM 128
#define BN 128
#define NTILE 4
#define THREADS 256

#define XTOT (E_ * N_ * R_)
#define WTOT (E_ * OUT_ * R_)

__device__ __half g_xh[XTOT];
__device__ __half g_wh[WTOT];

// Full-K regions: 128 rows x 128 fp16, row stride 272 B (256 data + 16 pad).
// 272 = 17*16 -> (17r + c) mod 8 permutation: ldmatrix and cp.async both
// bank-conflict-free.
#define RSTRIDE_B 272
#define REGION_B  (128 * RSTRIDE_B)         // 34816
#define SMEM_BYTES (3 * REGION_B)           // A + 2 B buffers = 104448

// ---------------- Kernel 1: fp32 -> fp16 ----------------
__global__ __launch_bounds__(256)
void convert_kernel(const float* __restrict__ X, const float* __restrict__ Wt)
{
    const int idx = blockIdx.x * blockDim.x + threadIdx.x;
    const int xq = XTOT / 4;
    const float4* src;
    uint2* dst;
    int base;
    if (idx < xq) {
        src = reinterpret_cast<const float4*>(X);
        dst = reinterpret_cast<uint2*>(g_xh);
        base = idx;
    } else {
        src = reinterpret_cast<const float4*>(Wt);
        dst = reinterpret_cast<uint2*>(g_wh);
        base = idx - xq;
    }
    float4 v = src[base];
    __half2 p0 = __floats2half2_rn(v.x, v.y);
    __half2 p1 = __floats2half2_rn(v.z, v.w);
    dst[base] = make_uint2(*reinterpret_cast<uint32_t*>(&p0),
                           *reinterpret_cast<uint32_t*>(&p1));
}

// ---------------- Kernel 2: GEMM ----------------
static __device__ __forceinline__ void mma_f16(float* d, const uint32_t* a,
                                               const uint32_t* b) {
    asm volatile(
        "mma.sync.aligned.m16n8k16.row.col.f32.f16.f16.f32 "
        "{%0,%1,%2,%3}, {%4,%5,%6,%7}, {%8,%9}, {%0,%1,%2,%3};"
        : "+f"(d[0]), "+f"(d[1]), "+f"(d[2]), "+f"(d[3])
        : "r"(a[0]), "r"(a[1]), "r"(a[2]), "r"(a[3]), "r"(b[0]), "r"(b[1]));
}

static __device__ __forceinline__ void ldsm4(uint32_t* r, uint32_t addr) {
    asm volatile("ldmatrix.sync.aligned.m8n8.x4.shared.b16 {%0,%1,%2,%3}, [%4];"
                 : "=r"(r[0]), "=r"(r[1]), "=r"(r[2]), "=r"(r[3]) : "r"(addr));
}

static __device__ __forceinline__ void cp16(uint32_t dst, const void* src) {
    asm volatile("cp.async.cg.shared.global [%0], [%1], 16;"
                 :: "r"(dst), "l"(src) : "memory");
}

static __device__ __forceinline__ uint32_t smem_u32(const void* p) {
    uint32_t a;
    asm("{ .reg .u64 t; cvta.to.shared.u64 t, %1; cvt.u32.u64 %0, t; }"
        : "=r"(a) : "l"(p));
    return a;
}

__global__ __launch_bounds__(THREADS, 2)
void moe_f16_mma_kernel(float* __restrict__ O)
{
    extern __shared__ char smem[];
    const uint32_t sbase = smem_u32(smem);
    const uint32_t sA = sbase;
    const uint32_t sB0 = sbase + REGION_B;
    const uint32_t sB1 = sbase + 2 * REGION_B;

    const int tid  = threadIdx.x;
    const int wid  = tid >> 5;
    const int lane = tid & 31;
    const int grp  = lane >> 2;
    const int qc   = lane & 3;
    const int wm   = wid >> 2;   // 0..1
    const int wn   = wid & 3;    // 0..3

    const int e   = blockIdx.z;
    const int bm  = blockIdx.y * BM;
    const int bn0 = blockIdx.x * (BN * NTILE);   // 512-wide stripe

    const __half* A  = g_xh + (size_t)e * N_   * R_ + (size_t)bm * R_;
    const __half* Bg = g_wh + (size_t)e * OUT_ * R_ + (size_t)bn0 * R_;
    float* C = O + (size_t)e * N_ * OUT_;

    // staging mapping: idx = tid + it*256; row = idx>>4, 16B-chunk c = idx&15
    // ldmatrix per-lane offsets
    const uint32_t a_loff = (uint32_t)((wm * 64 + (lane & 15)) * RSTRIDE_B
                                       + (lane >> 4) * 16);
    const uint32_t b_loff = (uint32_t)((wn * 32 + ((lane >> 4) & 1) * 8 + (lane & 7)) * RSTRIDE_B
                                       + ((lane >> 3) & 1) * 16);

    // ---- prologue: stage A + B0 (group 0), B1 (group 1) ----
#pragma unroll
    for (int it = 0; it < 8; it++) {
        const int idx = tid + it * THREADS;
        const int row = idx >> 4;
        const int c   = idx & 15;
        const uint32_t doff = (uint32_t)(row * RSTRIDE_B + c * 16);
        const int goff = row * R_ + c * 8;
        cp16(sA + doff, A + goff);
        cp16(sB0 + doff, Bg + goff);
    }
    asm volatile("cp.async.commit_group;" ::: "memory");
#pragma unroll
    for (int it = 0; it < 8; it++) {
        const int idx = tid + it * THREADS;
        const int row = idx >> 4;
        const int c   = idx & 15;
        cp16(sB1 + (uint32_t)(row * RSTRIDE_B + c * 16),
             Bg + (size_t)BM * R_ + row * R_ + c * 8);
    }
    asm volatile("cp.async.commit_group;" ::: "memory");

    uint32_t ah[2][16], bh[2][8];

#pragma unroll
    for (int t = 0; t < NTILE; t++) {
        if (t == 0) asm volatile("cp.async.wait_group 1;" ::: "memory");
        else        asm volatile("cp.async.wait_group 0;" ::: "memory");
        __syncthreads();   // B(t) visible to all; all warps done with buf(t&1)'s previous tile

        // stage B(t+2) into the buffer tile t just vacated... (t-2 used buf(t&1));
        // safe now: barrier above guarantees everyone finished compute(t-1),
        // and buf((t+2)&1) == buf(t&1) is the one being read THIS tile — so
        // stage B(t+2) only after this tile's compute; instead we stage B(t+1)'s
        // successor at the next loop head. Here: issue B(t+2)? No — issue at
        // head of t+1. (Double-buffer: one tile of lead.)
        if (t + 2 <= NTILE - 1 + 1 && t >= 1 && t + 1 < NTILE) {
            // at head of tile t (t>=1): buf((t+1)&1) was used by tile t-1,
            // everyone is past it -> stage B(t+1). Wait: B(t+1) already staged
            // at head of t? Manage explicitly below instead.
        }

        // Explicit staging schedule: at head of tile t (t>=1), stage B(t+1)
        // into buf((t+1)&1) (used last by tile t-1; barrier above protects it).
        if (t >= 1 && t + 1 < NTILE) {
            const uint32_t sb = (((t + 1) & 1) ? sB1 : sB0);
            const __half* Bt = Bg + (size_t)(t + 1) * BM * R_;
#pragma unroll
            for (int it = 0; it < 8; it++) {
                const int idx = tid + it * THREADS;
                const int row = idx >> 4;
                const int c   = idx & 15;
                cp16(sb + (uint32_t)(row * RSTRIDE_B + c * 16),
                     Bt + row * R_ + c * 8);
            }
            asm volatile("cp.async.commit_group;" ::: "memory");
        }

        const uint32_t bR = ((t & 1) ? sB1 : sB0);

        float acc[4][4][4];
#pragma unroll
        for (int mt = 0; mt < 4; mt++)
#pragma unroll
            for (int nt = 0; nt < 4; nt++)
#pragma unroll
                for (int q = 0; q < 4; q++)
                    acc[mt][nt][q] = 0.0f;

        // preload ks=0 fragments
        ldsm4(bh[0] + 0, bR + b_loff + 0 * 16 * RSTRIDE_B);
        ldsm4(bh[0] + 4, bR + b_loff + 1 * 16 * RSTRIDE_B);
#pragma unroll
        for (int mt = 0; mt < 4; mt++)
            ldsm4(ah[0] + mt * 4, sA + a_loff + (uint32_t)(mt * 16 * RSTRIDE_B));

#pragma unroll
        for (int ks = 0; ks < R_ / 16; ks++) {     // 8 k-steps
            const int cur = ks & 1;
            if (ks + 1 < R_ / 16) {
                const int nxt = cur ^ 1;
                const uint32_t kso = (uint32_t)((ks + 1) * 32);
                ldsm4(bh[nxt] + 0, bR + b_loff + 0 * 16 * RSTRIDE_B + kso);
                ldsm4(bh[nxt] + 4, bR + b_loff + 1 * 16 * RSTRIDE_B + kso);
#pragma unroll
                for (int mt = 0; mt < 4; mt++)
                    ldsm4(ah[nxt] + mt * 4,
                          sA + a_loff + (uint32_t)(mt * 16 * RSTRIDE_B) + kso);
            }
#pragma unroll
            for (int mt = 0; mt < 4; mt++)
#pragma unroll
                for (int nt = 0; nt < 4; nt++)
                    mma_f16(acc[mt][nt], ah[cur] + mt * 4, bh[cur] + nt * 2);
        }

        // ---- epilogue for tile t (streaming stores; drain overlaps tile t+1) ----
        const int colb = bn0 + t * BN;
#pragma unroll
        for (int mt = 0; mt < 4; mt++) {
#pragma unroll
            for (int nt = 0; nt < 4; nt++) {
                const int row = bm + wm * 64 + mt * 16 + grp;
                const int col = colb + wn * 32 + nt * 8 + qc * 2;
                float2 v0 = make_float2(acc[mt][nt][0], acc[mt][nt][1]);
                float2 v1 = make_float2(acc[mt][nt][2], acc[mt][nt][3]);
                __stcs(reinterpret_cast<float2*>(C + (size_t)row * OUT_ + col), v0);
                __stcs(reinterpret_cast<float2*>(C + (size_t)(row + 8) * OUT_ + col), v1);
            }
        }
    }
}

extern "C" void kernel_launch(void* const* d_in, const int* in_sizes, int n_in,
                              void* d_out, int out_size)
{
    const float* x = (const float*)d_in[0];   // [E, N, R]
    const float* w = (const float*)d_in[1];   // [E, OUT, R]
    float* out = (float*)d_out;               // [E, N, OUT]

    const int nvec = (XTOT + WTOT) / 4;
    convert_kernel<<<nvec / 256, 256>>>(x, w);

    cudaFuncSetAttribute(moe_f16_mma_kernel,
                         cudaFuncAttributeMaxDynamicSharedMemorySize, SMEM_BYTES);
    dim3 grid(OUT_ / (BN * NTILE), N_ / BM, E_);   // (8, 32, 8) = 2048 CTAs
    moe_f16_mma_kernel<<<grid, THREADS, SMEM_BYTES>>>(out);
}